// round 1
// baseline (speedup 1.0000x reference)
#include <cuda_runtime.h>
#include <math.h>

// Problem constants (PyTorchCG: BS=64, N=1024, maxiter derived from out_size)
#define CG_N  1024
#define CG_BS 64

// Persistent CG state across the kernels of one launch (no allocs allowed).
__device__ float g_r [CG_BS * CG_N];
__device__ float g_p [CG_BS * CG_N];
__device__ float g_Ap[CG_BS * CG_N];
__device__ float g_d [CG_BS * CG_N];   // diagonal of M_inv
__device__ float g_rz[CG_BS];

// ---------------------------------------------------------------------------
// Batched matvec: Av[b] = A[b] @ v[b].  One warp per row, float4 coalesced.
// grid = (N/8, BS), block = 256 (8 warps -> 8 rows per CTA).
// v == nullptr means "use g_p".
// ---------------------------------------------------------------------------
__global__ void k_matvec(const float* __restrict__ A, const float* __restrict__ v)
{
    __shared__ float4 sp[CG_N / 4];
    const int b   = blockIdx.y;
    const int tid = threadIdx.x;

    const float* vb = (v != nullptr) ? (v + (size_t)b * CG_N) : (g_p + (size_t)b * CG_N);
    sp[tid] = reinterpret_cast<const float4*>(vb)[tid];
    __syncthreads();

    const int warp = tid >> 5;
    const int lane = tid & 31;
    const int row  = (blockIdx.x << 3) + warp;

    const float4* Arow =
        reinterpret_cast<const float4*>(A + ((size_t)b * CG_N + row) * CG_N);

    float acc = 0.0f;
#pragma unroll
    for (int k = 0; k < CG_N / 128; ++k) {          // 8 float4 per lane
        float4 a = Arow[lane + 32 * k];
        float4 x = sp[lane + 32 * k];
        acc += a.x * x.x + a.y * x.y + a.z * x.z + a.w * x.w;
    }
#pragma unroll
    for (int off = 16; off; off >>= 1)
        acc += __shfl_xor_sync(0xffffffffu, acc, off);

    if (lane == 0) g_Ap[(size_t)b * CG_N + row] = acc;
}

// ---------------------------------------------------------------------------
// Deterministic block-wide sum over 256 threads.
// ---------------------------------------------------------------------------
__device__ __forceinline__ float block_sum(float v, float* sbuf)
{
    const int tid = threadIdx.x;
#pragma unroll
    for (int off = 16; off; off >>= 1)
        v += __shfl_xor_sync(0xffffffffu, v, off);
    if ((tid & 31) == 0) sbuf[tid >> 5] = v;
    __syncthreads();
    if (tid < 8) {
        float w = sbuf[tid];
#pragma unroll
        for (int off = 4; off; off >>= 1)
            w += __shfl_xor_sync(0x000000ffu, w, off);
        if (tid == 0) sbuf[0] = w;
    }
    __syncthreads();
    float r = sbuf[0];
    __syncthreads();
    return r;
}

// ---------------------------------------------------------------------------
// Init: extract diag(M_inv), r0 = b - A@x0 (g_Ap holds A@x0), z0 = d*r0,
// p0 = z0, rz0 = r0.z0, out[b][0] = ||r0||.   grid = BS, block = 256.
// ---------------------------------------------------------------------------
__global__ void k_init(const float* __restrict__ Minv,
                       const float* __restrict__ bvec,
                       float* __restrict__ out, int ldout)
{
    __shared__ float sbuf[8];
    const int b   = blockIdx.x;
    const int tid = threadIdx.x;
    const float* Mb = Minv + (size_t)b * CG_N * CG_N;

    float rz_p = 0.0f, rr_p = 0.0f;
#pragma unroll
    for (int k = 0; k < CG_N / 256; ++k) {
        const int i  = tid + 256 * k;
        const size_t gi = (size_t)b * CG_N + i;
        float dv = Mb[(size_t)i * CG_N + i];
        float rv = bvec[gi] - g_Ap[gi];
        float zv = dv * rv;
        g_d[gi] = dv;
        g_r[gi] = rv;
        g_p[gi] = zv;
        rz_p += rv * zv;
        rr_p += rv * rv;
    }
    float rz = block_sum(rz_p, sbuf);
    float rr = block_sum(rr_p, sbuf);
    if (tid == 0) {
        g_rz[b] = rz;
        out[(size_t)b * ldout] = sqrtf(rr);
    }
}

// ---------------------------------------------------------------------------
// One CG update after g_Ap = A@p:
//   alpha = rz / (p.Ap);  r -= alpha*Ap;  z = d*r;
//   beta = (r.z)_new / rz;  p = z + beta*p;  out[b][it+1] = ||r||.
// All vector state register-resident (4 elems/thread).  grid = BS, block = 256.
// ---------------------------------------------------------------------------
__global__ void k_update(float* __restrict__ out, int it, int ldout)
{
    __shared__ float sbuf[8];
    const int b   = blockIdx.x;
    const int tid = threadIdx.x;

    const float rz_old = g_rz[b];   // read BEFORE any barrier; rewritten only at end

    float pv[4], apv[4], rv[4], dv[4];
    float pap_p = 0.0f;
#pragma unroll
    for (int k = 0; k < 4; ++k) {
        const size_t i = (size_t)b * CG_N + tid + 256 * k;
        pv[k]  = g_p[i];
        apv[k] = g_Ap[i];
        pap_p += pv[k] * apv[k];
    }
    const float pAp   = block_sum(pap_p, sbuf);
    const float alpha = rz_old / pAp;

    float rz_p = 0.0f, rr_p = 0.0f;
#pragma unroll
    for (int k = 0; k < 4; ++k) {
        const size_t i = (size_t)b * CG_N + tid + 256 * k;
        rv[k] = g_r[i] - alpha * apv[k];
        dv[k] = g_d[i];
        g_r[i] = rv[k];
        const float zv = dv[k] * rv[k];
        rz_p += rv[k] * zv;
        rr_p += rv[k] * rv[k];
    }
    const float rz_new = block_sum(rz_p, sbuf);
    const float rr     = block_sum(rr_p, sbuf);
    const float beta   = rz_new / rz_old;

#pragma unroll
    for (int k = 0; k < 4; ++k) {
        const size_t i = (size_t)b * CG_N + tid + 256 * k;
        g_p[i] = dv[k] * rv[k] + beta * pv[k];
    }

    if (tid == 0) {
        g_rz[b] = rz_new;
        out[(size_t)b * ldout + it + 1] = sqrtf(rr);
    }
}

// ---------------------------------------------------------------------------
// kernel_launch: graph-capturable sequence of ~103 kernel launches.
// Inputs: A (BS*N*N), b (BS*N), x0 (BS*N), M_inv (BS*N*N), rtol (BS), maxiter.
// rtol is unused by the reference scan; maxiter derived from out_size.
// ---------------------------------------------------------------------------
extern "C" void kernel_launch(void* const* d_in, const int* in_sizes, int n_in,
                              void* d_out, int out_size)
{
    const float* A    = (const float*)d_in[0];
    const float* bvec = (const float*)d_in[1];
    const float* x0   = (const float*)d_in[2];
    const float* Minv = (const float*)d_in[3];
    float* out        = (float*)d_out;

    const int ldout   = out_size / CG_BS;   // maxiter + 1
    const int maxiter = ldout - 1;

    dim3 grid_mv(CG_N / 8, CG_BS);

    // r0 = b - A @ x0
    k_matvec<<<grid_mv, 256>>>(A, x0);
    k_init<<<CG_BS, 256>>>(Minv, bvec, out, ldout);

    for (int it = 0; it < maxiter; ++it) {
        k_matvec<<<grid_mv, 256>>>(A, nullptr);   // Ap = A @ p
        k_update<<<CG_BS, 256>>>(out, it, ldout);
    }
}